// round 2
// baseline (speedup 1.0000x reference)
#include <cuda_runtime.h>
#include <math_constants.h>

// Problem constants
#define NBATCH 2
#define TSEQ   2048
#define DMODEL 1024
#define NH     16
#define DH     64
#define DFF    4096
#define MTOK   (NBATCH * TSEQ)   // 4096 rows

// ---------------- scratch (static device arrays; no allocation) ----------------
__device__ float g_h   [MTOK * DMODEL];     // rmsnorm output (reused for h2)
__device__ float g_qkv [MTOK * 3 * DMODEL]; // qkv projection
__device__ float g_q   [MTOK * DMODEL];     // q in [B,H,T,DH]
__device__ float g_attn[MTOK * DMODEL];     // attention out in [B,T,H*DH]
__device__ float g_x1  [MTOK * DMODEL];     // residual after proj
__device__ float g_gate[MTOK * DFF];        // gate gemm out -> silu*up in place
__device__ float g_up  [MTOK * DFF];        // up gemm out

// ---------------- RMSNorm: one block per row, 256 threads, float4 ----------------
// SRC: 0 = read from param x ; 1 = read from g_x1.   Always writes g_h.
template <int SRC>
__global__ __launch_bounds__(256) void rmsnorm_kernel(
    const float* __restrict__ xin, const float* __restrict__ w) {
  const float* __restrict__ x = (SRC == 0) ? xin : g_x1;
  const int row = blockIdx.x;
  const int t = threadIdx.x;
  const float4 v = reinterpret_cast<const float4*>(x)[row * 256 + t];
  float ss = v.x * v.x + v.y * v.y + v.z * v.z + v.w * v.w;
#pragma unroll
  for (int o = 16; o > 0; o >>= 1) ss += __shfl_xor_sync(0xffffffffu, ss, o);
  __shared__ float sbuf[8];
  if ((t & 31) == 0) sbuf[t >> 5] = ss;
  __syncthreads();
  float tot = sbuf[0] + sbuf[1] + sbuf[2] + sbuf[3] + sbuf[4] + sbuf[5] + sbuf[6] + sbuf[7];
  const float r = rsqrtf(tot * (1.0f / DMODEL) + 1e-6f);
  const float4 wv = reinterpret_cast<const float4*>(w)[t];
  float4 o4 = make_float4(v.x * r * wv.x, v.y * r * wv.y, v.z * r * wv.z, v.w * r * wv.w);
  reinterpret_cast<float4*>(g_h)[row * 256 + t] = o4;
}

// ---------------- GEMM (NT): C[M,N] = A[M,K] @ B[N,K]^T  (+ optional residual) ----
// BM=BN=128, BK=16, 256 threads, 8x8 microtile, software-pipelined prefetch.
// ASEL: 0=g_h 1=g_attn 2=g_gate ; CSEL: 0=g_qkv 1=g_x1 2=g_gate 3=g_up 4=param
// RSEL: 0=none 1=param 2=g_x1
template <int ASEL, int CSEL, int RSEL>
__global__ __launch_bounds__(256) void gemm_nt(
    const float* __restrict__ Bw, float* __restrict__ Cext,
    const float* __restrict__ Rext, int M, int N, int K) {
  const float* __restrict__ A = (ASEL == 0) ? g_h : (ASEL == 1) ? g_attn : g_gate;
  float* __restrict__ C = (CSEL == 0) ? g_qkv : (CSEL == 1) ? g_x1
                        : (CSEL == 2) ? g_gate : (CSEL == 3) ? g_up : Cext;
  const float* __restrict__ R = (RSEL == 2) ? g_x1 : Rext;

  __shared__ float As[16][132];
  __shared__ float Bs[16][132];
  const int bm = blockIdx.y * 128;
  const int bn = blockIdx.x * 128;
  const int tid = threadIdx.x;
  const int lr = tid >> 2;            // 0..63
  const int lc = (tid & 3) << 2;      // 0,4,8,12
  const float* Ap = A  + (size_t)(bm + lr) * K + lc;
  const float* Bp = Bw + (size_t)(bn + lr) * K + lc;
  const int tm = (tid >> 4) << 3;     // 0..120
  const int tn = (tid & 15) << 3;     // 0..120

  float acc[8][8];
#pragma unroll
  for (int i = 0; i < 8; i++)
#pragma unroll
    for (int j = 0; j < 8; j++) acc[i][j] = 0.0f;

  // preload tile 0
  float4 a0 = *reinterpret_cast<const float4*>(Ap);
  float4 a1 = *reinterpret_cast<const float4*>(Ap + (size_t)64 * K);
  float4 b0 = *reinterpret_cast<const float4*>(Bp);
  float4 b1 = *reinterpret_cast<const float4*>(Bp + (size_t)64 * K);
  As[lc + 0][lr] = a0.x; As[lc + 1][lr] = a0.y; As[lc + 2][lr] = a0.z; As[lc + 3][lr] = a0.w;
  As[lc + 0][lr + 64] = a1.x; As[lc + 1][lr + 64] = a1.y; As[lc + 2][lr + 64] = a1.z; As[lc + 3][lr + 64] = a1.w;
  Bs[lc + 0][lr] = b0.x; Bs[lc + 1][lr] = b0.y; Bs[lc + 2][lr] = b0.z; Bs[lc + 3][lr] = b0.w;
  Bs[lc + 0][lr + 64] = b1.x; Bs[lc + 1][lr + 64] = b1.y; Bs[lc + 2][lr + 64] = b1.z; Bs[lc + 3][lr + 64] = b1.w;
  __syncthreads();

  for (int k0 = 16; k0 <= K; k0 += 16) {
    const bool more = (k0 < K);
    if (more) {  // prefetch next tile into registers; latency hidden under compute
      Ap += 16; Bp += 16;
      a0 = *reinterpret_cast<const float4*>(Ap);
      a1 = *reinterpret_cast<const float4*>(Ap + (size_t)64 * K);
      b0 = *reinterpret_cast<const float4*>(Bp);
      b1 = *reinterpret_cast<const float4*>(Bp + (size_t)64 * K);
    }
#pragma unroll
    for (int kk = 0; kk < 16; kk++) {
      float ar[8], br[8];
      *reinterpret_cast<float4*>(ar)     = *reinterpret_cast<const float4*>(&As[kk][tm]);
      *reinterpret_cast<float4*>(ar + 4) = *reinterpret_cast<const float4*>(&As[kk][tm + 4]);
      *reinterpret_cast<float4*>(br)     = *reinterpret_cast<const float4*>(&Bs[kk][tn]);
      *reinterpret_cast<float4*>(br + 4) = *reinterpret_cast<const float4*>(&Bs[kk][tn + 4]);
#pragma unroll
      for (int i = 0; i < 8; i++)
#pragma unroll
        for (int j = 0; j < 8; j++) acc[i][j] += ar[i] * br[j];
    }
    if (more) {
      __syncthreads();
      As[lc + 0][lr] = a0.x; As[lc + 1][lr] = a0.y; As[lc + 2][lr] = a0.z; As[lc + 3][lr] = a0.w;
      As[lc + 0][lr + 64] = a1.x; As[lc + 1][lr + 64] = a1.y; As[lc + 2][lr + 64] = a1.z; As[lc + 3][lr + 64] = a1.w;
      Bs[lc + 0][lr] = b0.x; Bs[lc + 1][lr] = b0.y; Bs[lc + 2][lr] = b0.z; Bs[lc + 3][lr] = b0.w;
      Bs[lc + 0][lr + 64] = b1.x; Bs[lc + 1][lr + 64] = b1.y; Bs[lc + 2][lr + 64] = b1.z; Bs[lc + 3][lr + 64] = b1.w;
      __syncthreads();
    }
  }

#pragma unroll
  for (int i = 0; i < 8; i++) {
    const size_t co = (size_t)(bm + tm + i) * N + bn + tn;
    float4 c0 = make_float4(acc[i][0], acc[i][1], acc[i][2], acc[i][3]);
    float4 c1 = make_float4(acc[i][4], acc[i][5], acc[i][6], acc[i][7]);
    if (RSEL != 0) {
      const float4 r0 = *reinterpret_cast<const float4*>(R + co);
      const float4 r1 = *reinterpret_cast<const float4*>(R + co + 4);
      c0.x += r0.x; c0.y += r0.y; c0.z += r0.z; c0.w += r0.w;
      c1.x += r1.x; c1.y += r1.y; c1.z += r1.z; c1.w += r1.w;
    }
    *reinterpret_cast<float4*>(C + co)     = c0;
    *reinterpret_cast<float4*>(C + co + 4) = c1;
  }
}

// ---------------- scatter qkv -> q[B,H,T,DH], k_cache, v_cache ----------------
__global__ __launch_bounds__(256) void scatter_qkv_kernel(float* __restrict__ kc,
                                                          float* __restrict__ vc) {
  const int idx = blockIdx.x * 256 + threadIdx.x;       // over MTOK*768 float4s
  const float4 v = reinterpret_cast<const float4*>(g_qkv)[idx];
  const int row = idx / 768;               // b*T + t
  const int col = (idx - row * 768) << 2;  // 0..3071
  const int s  = col >> 10;                // 0:q 1:k 2:v
  const int hd = col & 1023;               // h*64 + dh
  const int b  = row >> 11;
  const int t  = row & 2047;
  const size_t dst = ((size_t)(b * NH + (hd >> 6)) * TSEQ + t) * DH + (hd & 63);
  float* base = (s == 0) ? g_q : (s == 1) ? kc : vc;
  *reinterpret_cast<float4*>(base + dst) = v;
}

// ---------------- flash attention (fp32, causal), 64x64 tiles ----------------
// grid: (T/64, B*H), 256 threads arranged 16x16, each owns 4x4 of S/O.
__global__ __launch_bounds__(256) void attention_kernel(const float* __restrict__ kc,
                                                        const float* __restrict__ vc) {
  __shared__ float Qt[64][64];  // Qt[d][r], pre-scaled by 1/sqrt(DH)
  __shared__ float KV[64][64];  // Kt[d][c] during S, Vs[k][c] during PV
  __shared__ float Pt[64][64];  // Pt[k][r]
  const int qx  = blockIdx.x;
  const int bh  = blockIdx.y;
  const int tid = threadIdx.x;
  const int tr = tid >> 4, tc = tid & 15;
  const int r0 = tr << 2, c0 = tc << 2;
  const size_t base = (size_t)bh * TSEQ * DH;
  const float* qp = g_q + base + (size_t)qx * 64 * DH;

  // load Q transposed + scaled
#pragma unroll
  for (int it = 0; it < 4; it++) {
    const int idx = tid + it * 256;
    const int rr = idx >> 4;
    const int d4 = (idx & 15) << 2;
    const float4 v = *reinterpret_cast<const float4*>(qp + rr * DH + d4);
    Qt[d4 + 0][rr] = v.x * 0.125f;
    Qt[d4 + 1][rr] = v.y * 0.125f;
    Qt[d4 + 2][rr] = v.z * 0.125f;
    Qt[d4 + 3][rr] = v.w * 0.125f;
  }

  float o[4][4];
#pragma unroll
  for (int i = 0; i < 4; i++)
#pragma unroll
    for (int j = 0; j < 4; j++) o[i][j] = 0.0f;
  float mrow[4] = {-CUDART_INF_F, -CUDART_INF_F, -CUDART_INF_F, -CUDART_INF_F};
  float lrow[4] = {0.0f, 0.0f, 0.0f, 0.0f};

  for (int jt = 0; jt <= qx; jt++) {
    const float* kp = kc + base + (size_t)jt * 64 * DH;
    __syncthreads();  // previous tile's Pt/V reads done before overwrite
#pragma unroll
    for (int it = 0; it < 4; it++) {
      const int idx = tid + it * 256;
      const int cc = idx >> 4;
      const int d4 = (idx & 15) << 2;
      const float4 v = *reinterpret_cast<const float4*>(kp + cc * DH + d4);
      KV[d4 + 0][cc] = v.x; KV[d4 + 1][cc] = v.y; KV[d4 + 2][cc] = v.z; KV[d4 + 3][cc] = v.w;
    }
    __syncthreads();

    float s[4][4];
#pragma unroll
    for (int i = 0; i < 4; i++)
#pragma unroll
      for (int j = 0; j < 4; j++) s[i][j] = 0.0f;
#pragma unroll
    for (int d = 0; d < 64; d++) {
      const float4 qv = *reinterpret_cast<const float4*>(&Qt[d][r0]);
      const float4 kv = *reinterpret_cast<const float4*>(&KV[d][c0]);
      const float qa[4] = {qv.x, qv.y, qv.z, qv.w};
      const float ka[4] = {kv.x, kv.y, kv.z, kv.w};
#pragma unroll
      for (int i = 0; i < 4; i++)
#pragma unroll
        for (int j = 0; j < 4; j++) s[i][j] += qa[i] * ka[j];
    }
    if (jt == qx) {  // causal mask on the diagonal tile only
#pragma unroll
      for (int i = 0; i < 4; i++)
#pragma unroll
        for (int j = 0; j < 4; j++)
          if (c0 + j > r0 + i) s[i][j] = -CUDART_INF_F;
    }

    float rm[4], rs[4], mnew[4], alpha[4];
#pragma unroll
    for (int i = 0; i < 4; i++) {
      rm[i] = fmaxf(fmaxf(s[i][0], s[i][1]), fmaxf(s[i][2], s[i][3]));
    }
#pragma unroll
    for (int off = 8; off > 0; off >>= 1)
#pragma unroll
      for (int i = 0; i < 4; i++)
        rm[i] = fmaxf(rm[i], __shfl_xor_sync(0xffffffffu, rm[i], off));
#pragma unroll
    for (int i = 0; i < 4; i++) {
      mnew[i]  = fmaxf(mrow[i], rm[i]);
      alpha[i] = __expf(mrow[i] - mnew[i]);
      mrow[i]  = mnew[i];
      rs[i]    = 0.0f;
    }
#pragma unroll
    for (int i = 0; i < 4; i++)
#pragma unroll
      for (int j = 0; j < 4; j++) {
        const float p = __expf(s[i][j] - mnew[i]);
        Pt[c0 + j][r0 + i] = p;
        rs[i] += p;
      }
#pragma unroll
    for (int off = 8; off > 0; off >>= 1)
#pragma unroll
      for (int i = 0; i < 4; i++)
        rs[i] += __shfl_xor_sync(0xffffffffu, rs[i], off);
#pragma unroll
    for (int i = 0; i < 4; i++) {
      lrow[i] = lrow[i] * alpha[i] + rs[i];
#pragma unroll
      for (int j = 0; j < 4; j++) o[i][j] *= alpha[i];
    }
    __syncthreads();  // Pt complete; Kt no longer needed

    const float* vp = vc + base + (size_t)jt * 64 * DH;
#pragma unroll
    for (int it = 0; it < 4; it++) {
      const int idx = tid + it * 256;
      const int kk = idx >> 4;
      const int d4 = (idx & 15) << 2;
      *reinterpret_cast<float4*>(&KV[kk][d4]) =
          *reinterpret_cast<const float4*>(vp + kk * DH + d4);
    }
    __syncthreads();
#pragma unroll
    for (int k = 0; k < 64; k++) {
      const float4 pv = *reinterpret_cast<const float4*>(&Pt[k][r0]);
      const float4 vv = *reinterpret_cast<const float4*>(&KV[k][c0]);
      const float pa[4] = {pv.x, pv.y, pv.z, pv.w};
      const float va[4] = {vv.x, vv.y, vv.z, vv.w};
#pragma unroll
      for (int i = 0; i < 4; i++)
#pragma unroll
        for (int j = 0; j < 4; j++) o[i][j] += pa[i] * va[j];
    }
  }

  // write O / l  into g_attn laid out [B,T,H*DH]
  const int b = bh >> 4, h = bh & 15;
#pragma unroll
  for (int i = 0; i < 4; i++) {
    const float inv = 1.0f / lrow[i];
    const int t = qx * 64 + r0 + i;
    const size_t off = ((size_t)(b * TSEQ + t)) * DMODEL + h * DH + c0;
    float4 ov = make_float4(o[i][0] * inv, o[i][1] * inv, o[i][2] * inv, o[i][3] * inv);
    *reinterpret_cast<float4*>(g_attn + off) = ov;
  }
}

// ---------------- silu(gate) * up, in place into g_gate ----------------
__global__ __launch_bounds__(256) void silu_mul_kernel() {
  const int idx = blockIdx.x * 256 + threadIdx.x;  // MTOK*DFF/4 float4s
  float4 g = reinterpret_cast<const float4*>(g_gate)[idx];
  const float4 u = reinterpret_cast<const float4*>(g_up)[idx];
  g.x = (g.x / (1.0f + __expf(-g.x))) * u.x;
  g.y = (g.y / (1.0f + __expf(-g.y))) * u.y;
  g.z = (g.z / (1.0f + __expf(-g.z))) * u.z;
  g.w = (g.w / (1.0f + __expf(-g.w))) * u.w;
  reinterpret_cast<float4*>(g_gate)[idx] = g;
}

// ---------------- launch (pure kernel launches; graph-capture safe) -----------
extern "C" void kernel_launch(void* const* d_in, const int* in_sizes, int n_in,
                              void* d_out, int out_size) {
  const float* x       = (const float*)d_in[0];
  const float* w_norm1 = (const float*)d_in[1];
  const float* w_qkv   = (const float*)d_in[2];
  const float* w_proj  = (const float*)d_in[3];
  const float* w_norm2 = (const float*)d_in[4];
  const float* w_gate  = (const float*)d_in[5];
  const float* w_up    = (const float*)d_in[6];
  const float* w_down  = (const float*)d_in[7];
  // d_in[8] = step (0 in prefill) — unused

  float* out_x = (float*)d_out;                       // [B,T,D]
  float* kc    = out_x + (size_t)MTOK * DMODEL;       // [B,H,CTX,DH]
  float* vc    = kc    + (size_t)MTOK * DMODEL;       // [B,H,CTX,DH]

  // 1) h = rmsnorm(x) * w_norm1
  rmsnorm_kernel<0><<<MTOK, 256>>>(x, w_norm1);
  // 2) qkv = h @ w_qkv^T
  gemm_nt<0, 0, 0><<<dim3(3 * DMODEL / 128, MTOK / 128), 256>>>(
      w_qkv, nullptr, nullptr, MTOK, 3 * DMODEL, DMODEL);
  // 3) scatter q / k_cache / v_cache
  scatter_qkv_kernel<<<MTOK * 768 / 256, 256>>>(kc, vc);
  // 4) causal flash attention -> g_attn [B,T,H*DH]
  attention_kernel<<<dim3(TSEQ / 64, NBATCH * NH), 256>>>(kc, vc);
  // 5) x1 = attn @ w_proj^T + x
  gemm_nt<1, 1, 1><<<dim3(DMODEL / 128, MTOK / 128), 256>>>(
      w_proj, nullptr, x, MTOK, DMODEL, DMODEL);
  // 6) h2 = rmsnorm(x1) * w_norm2
  rmsnorm_kernel<1><<<MTOK, 256>>>(nullptr, w_norm2);
  // 7) gate / up GEMMs
  gemm_nt<0, 2, 0><<<dim3(DFF / 128, MTOK / 128), 256>>>(
      w_gate, nullptr, nullptr, MTOK, DFF, DMODEL);
  gemm_nt<0, 3, 0><<<dim3(DFF / 128, MTOK / 128), 256>>>(
      w_up, nullptr, nullptr, MTOK, DFF, DMODEL);
  // 8) act = silu(gate) * up  (in place in g_gate)
  silu_mul_kernel<<<MTOK * DFF / 4 / 256, 256>>>();
  // 9) out_x = act @ w_down^T + x1
  gemm_nt<2, 4, 2><<<dim3(DMODEL / 128, MTOK / 128), 256>>>(
      w_down, out_x, nullptr, MTOK, DMODEL, DFF);
}

// round 5
// speedup vs baseline: 1.3474x; 1.3474x over previous
#include <cuda_runtime.h>
#include <cuda_bf16.h>
#include <math_constants.h>
#include <cstdint>

// Problem constants
#define NBATCH 2
#define TSEQ   2048
#define DMODEL 1024
#define NH     16
#define DH     64
#define DFF    4096
#define MTOK   (NBATCH * TSEQ)   // 4096 rows

// ---------------- scratch (static device arrays; no allocation) ----------------
__device__ float g_h   [MTOK * DMODEL];
__device__ float g_qkv [MTOK * 3 * DMODEL];
__device__ float g_q   [MTOK * DMODEL];
__device__ float g_attn[MTOK * DMODEL];
__device__ float g_x1  [MTOK * DMODEL];
__device__ float g_gate[MTOK * DFF];
__device__ float g_up  [MTOK * DFF];

// ==================== bf16 helpers ====================
__device__ __forceinline__ uint32_t pack_bf2(__nv_bfloat16 lo, __nv_bfloat16 hi) {
  __nv_bfloat162 t;
  t.x = lo;  // low 16 bits = first (smaller k) element
  t.y = hi;
  return *reinterpret_cast<uint32_t*>(&t);
}

// split x = hi + lo (both bf16), hi = rn(x), lo = rn(x - hi)
__device__ __forceinline__ void split_bf(float x, __nv_bfloat16& h, __nv_bfloat16& l) {
  h = __float2bfloat16_rn(x);
  l = __float2bfloat16_rn(x - __bfloat162float(h));
}

// mma.sync m16n8k16 row.col f32.bf16.bf16.f32
__device__ __forceinline__ void mma16816(float* c, const uint32_t* a, uint32_t b0, uint32_t b1) {
  asm("mma.sync.aligned.m16n8k16.row.col.f32.bf16.bf16.f32 "
      "{%0,%1,%2,%3}, {%4,%5,%6,%7}, {%8,%9}, {%0,%1,%2,%3};"
      : "+f"(c[0]), "+f"(c[1]), "+f"(c[2]), "+f"(c[3])
      : "r"(a[0]), "r"(a[1]), "r"(a[2]), "r"(a[3]), "r"(b0), "r"(b1));
}

// ==================== bf16 3-split tensor-core GEMM ====================
// C[M,N] = A[M,K] @ B[N,K]^T (+ optional residual)
// CTA tile 128x128, BK=32, 256 threads (8 warps, 2m x 4n), warp tile 64x32.
// smem per stage: A_hi, A_lo, B_hi, B_lo each [128][36] bf16 (pad 36 for banks).
// ASEL: 0=g_h 1=g_attn 2=g_gate ; CSEL: 0=g_qkv 1=g_x1 2=g_gate 3=g_up 4=param
// RSEL: 0=none 1=param 2=g_x1
#define GB_ROWPAD   36
#define GB_MAT      (128 * GB_ROWPAD * 2)   // 9216 bytes per bf16 matrix
#define GB_STAGE    (4 * GB_MAT)            // 36864
#define GB_SMEM     (2 * GB_STAGE)          // 73728

template <int KDIM, int ASEL, int CSEL, int RSEL>
__global__ __launch_bounds__(256, 1) void gemm_bf3(
    const float* __restrict__ Bw, float* __restrict__ Cext,
    const float* __restrict__ Rext, int N) {
  constexpr int NCH = KDIM / 32;
  const float* __restrict__ A = (ASEL == 0) ? g_h : (ASEL == 1) ? g_attn : g_gate;
  float* __restrict__ C = (CSEL == 0) ? g_qkv : (CSEL == 1) ? g_x1
                        : (CSEL == 2) ? g_gate : (CSEL == 3) ? g_up : Cext;
  const float* __restrict__ R = (RSEL == 2) ? g_x1 : Rext;

  extern __shared__ __align__(16) char smem[];
  const int tid = threadIdx.x;
  const int wid = tid >> 5, lane = tid & 31;
  const int wm = wid >> 2, wn = wid & 3;       // warp grid 2 x 4
  const int r = lane >> 2, cq = lane & 3;      // quad row / quad col
  const int bm = blockIdx.y * 128, bn = blockIdx.x * 128;

  // loader mapping: each thread loads 4 float4 of A and 4 of B per chunk
  const int lrow = tid >> 1;                   // 0..127
  const int lq   = (tid & 1) * 16;             // k offset 0 or 16
  const float* Ap = A  + (size_t)(bm + lrow) * KDIM + lq;
  const float* Bp = Bw + (size_t)(bn + lrow) * KDIM + lq;

  float acc[4][4][4];
#pragma unroll
  for (int f = 0; f < 4; f++)
#pragma unroll
    for (int n = 0; n < 4; n++)
#pragma unroll
      for (int i = 0; i < 4; i++) acc[f][n][i] = 0.0f;

  float4 av[4], bv[4];
#pragma unroll
  for (int i = 0; i < 4; i++) {
    av[i] = *reinterpret_cast<const float4*>(Ap + 4 * i);
    bv[i] = *reinterpret_cast<const float4*>(Bp + 4 * i);
  }

  for (int ch = 0; ch < NCH; ++ch) {
    char* stage = smem + (ch & 1) * GB_STAGE;
    // --- split + store current chunk to smem (bf16 hi/lo) ---
#pragma unroll
    for (int i = 0; i < 4; i++) {
      const int k0 = lq + 4 * i;
      const uint32_t boff = (uint32_t)(lrow * GB_ROWPAD + k0) * 2u;
      __nv_bfloat16 hx, lx, hy, ly, hz, lz, hw, lw;
      // A
      split_bf(av[i].x, hx, lx); split_bf(av[i].y, hy, ly);
      split_bf(av[i].z, hz, lz); split_bf(av[i].w, hw, lw);
      *reinterpret_cast<uint2*>(stage + 0 * GB_MAT + boff) =
          make_uint2(pack_bf2(hx, hy), pack_bf2(hz, hw));
      *reinterpret_cast<uint2*>(stage + 1 * GB_MAT + boff) =
          make_uint2(pack_bf2(lx, ly), pack_bf2(lz, lw));
      // B
      split_bf(bv[i].x, hx, lx); split_bf(bv[i].y, hy, ly);
      split_bf(bv[i].z, hz, lz); split_bf(bv[i].w, hw, lw);
      *reinterpret_cast<uint2*>(stage + 2 * GB_MAT + boff) =
          make_uint2(pack_bf2(hx, hy), pack_bf2(hz, hw));
      *reinterpret_cast<uint2*>(stage + 3 * GB_MAT + boff) =
          make_uint2(pack_bf2(lx, ly), pack_bf2(lz, lw));
    }
    __syncthreads();

    if (ch + 1 < NCH) {  // prefetch next chunk (latency hidden under MMA)
      const float* Ap2 = Ap + (ch + 1) * 32;
      const float* Bp2 = Bp + (ch + 1) * 32;
#pragma unroll
      for (int i = 0; i < 4; i++) {
        av[i] = *reinterpret_cast<const float4*>(Ap2 + 4 * i);
        bv[i] = *reinterpret_cast<const float4*>(Bp2 + 4 * i);
      }
    }

    // --- MMA on this stage ---
    const uint32_t* pAH = reinterpret_cast<const uint32_t*>(stage + 0 * GB_MAT);
    const uint32_t* pAL = reinterpret_cast<const uint32_t*>(stage + 1 * GB_MAT);
    const uint32_t* pBH = reinterpret_cast<const uint32_t*>(stage + 2 * GB_MAT);
    const uint32_t* pBL = reinterpret_cast<const uint32_t*>(stage + 3 * GB_MAT);
#pragma unroll
    for (int ks = 0; ks < 2; ks++) {
      const int kc = ks * 8 + cq;              // u32 col index within row
      uint32_t ah[4][4], al[4][4];
#pragma unroll
      for (int f = 0; f < 4; f++) {
        const int base = (wm * 64 + f * 16 + r) * (GB_ROWPAD / 2) + kc;
        ah[f][0] = pAH[base];       ah[f][1] = pAH[base + 8 * (GB_ROWPAD / 2)];
        ah[f][2] = pAH[base + 4];   ah[f][3] = pAH[base + 8 * (GB_ROWPAD / 2) + 4];
        al[f][0] = pAL[base];       al[f][1] = pAL[base + 8 * (GB_ROWPAD / 2)];
        al[f][2] = pAL[base + 4];   al[f][3] = pAL[base + 8 * (GB_ROWPAD / 2) + 4];
      }
#pragma unroll
      for (int nf = 0; nf < 4; nf++) {
        const int bb = (wn * 32 + nf * 8 + r) * (GB_ROWPAD / 2) + kc;
        const uint32_t bh0 = pBH[bb], bh1 = pBH[bb + 4];
        const uint32_t bl0 = pBL[bb], bl1 = pBL[bb + 4];
#pragma unroll
        for (int f = 0; f < 4; f++) {
          mma16816(acc[f][nf], ah[f], bh0, bh1);
          mma16816(acc[f][nf], ah[f], bl0, bl1);
          mma16816(acc[f][nf], al[f], bh0, bh1);
        }
      }
    }
    __syncthreads();
  }

  // --- epilogue: float2 stores, optional residual ---
#pragma unroll
  for (int f = 0; f < 4; f++) {
    const int row0 = bm + wm * 64 + f * 16 + r;
#pragma unroll
    for (int nf = 0; nf < 4; nf++) {
      const int col = bn + wn * 32 + nf * 8 + cq * 2;
      const size_t o0 = (size_t)row0 * N + col;
      const size_t o1 = o0 + (size_t)8 * N;
      float2 v0 = make_float2(acc[f][nf][0], acc[f][nf][1]);
      float2 v1 = make_float2(acc[f][nf][2], acc[f][nf][3]);
      if (RSEL != 0) {
        const float2 r0 = *reinterpret_cast<const float2*>(R + o0);
        const float2 r1 = *reinterpret_cast<const float2*>(R + o1);
        v0.x += r0.x; v0.y += r0.y; v1.x += r1.x; v1.y += r1.y;
      }
      *reinterpret_cast<float2*>(C + o0) = v0;
      *reinterpret_cast<float2*>(C + o1) = v1;
    }
  }
}

// ---------------- RMSNorm ----------------
template <int SRC>
__global__ __launch_bounds__(256) void rmsnorm_kernel(
    const float* __restrict__ xin, const float* __restrict__ w) {
  const float* __restrict__ x = (SRC == 0) ? xin : g_x1;
  const int row = blockIdx.x;
  const int t = threadIdx.x;
  const float4 v = reinterpret_cast<const float4*>(x)[row * 256 + t];
  float ss = v.x * v.x + v.y * v.y + v.z * v.z + v.w * v.w;
#pragma unroll
  for (int o = 16; o > 0; o >>= 1) ss += __shfl_xor_sync(0xffffffffu, ss, o);
  __shared__ float sbuf[8];
  if ((t & 31) == 0) sbuf[t >> 5] = ss;
  __syncthreads();
  float tot = sbuf[0] + sbuf[1] + sbuf[2] + sbuf[3] + sbuf[4] + sbuf[5] + sbuf[6] + sbuf[7];
  const float r = rsqrtf(tot * (1.0f / DMODEL) + 1e-6f);
  const float4 wv = reinterpret_cast<const float4*>(w)[t];
  float4 o4 = make_float4(v.x * r * wv.x, v.y * r * wv.y, v.z * r * wv.z, v.w * r * wv.w);
  reinterpret_cast<float4*>(g_h)[row * 256 + t] = o4;
}

// ---------------- scatter qkv ----------------
__global__ __launch_bounds__(256) void scatter_qkv_kernel(float* __restrict__ kc,
                                                          float* __restrict__ vc) {
  const int idx = blockIdx.x * 256 + threadIdx.x;
  const float4 v = reinterpret_cast<const float4*>(g_qkv)[idx];
  const int row = idx / 768;
  const int col = (idx - row * 768) << 2;
  const int s  = col >> 10;
  const int hd = col & 1023;
  const int b  = row >> 11;
  const int t  = row & 2047;
  const size_t dst = ((size_t)(b * NH + (hd >> 6)) * TSEQ + t) * DH + (hd & 63);
  float* base = (s == 0) ? g_q : (s == 1) ? kc : vc;
  *reinterpret_cast<float4*>(base + dst) = v;
}

// ---------------- flash attention (fp32, causal), 64x64 tiles ----------------
__global__ __launch_bounds__(256) void attention_kernel(const float* __restrict__ kc,
                                                        const float* __restrict__ vc) {
  __shared__ float Qt[64][64];
  __shared__ float KV[64][64];
  __shared__ float Pt[64][64];
  const int qx  = blockIdx.x;
  const int bh  = blockIdx.y;
  const int tid = threadIdx.x;
  const int tr = tid >> 4, tc = tid & 15;
  const int r0 = tr << 2, c0 = tc << 2;
  const size_t base = (size_t)bh * TSEQ * DH;
  const float* qp = g_q + base + (size_t)qx * 64 * DH;

#pragma unroll
  for (int it = 0; it < 4; it++) {
    const int idx = tid + it * 256;
    const int rr = idx >> 4;
    const int d4 = (idx & 15) << 2;
    const float4 v = *reinterpret_cast<const float4*>(qp + rr * DH + d4);
    Qt[d4 + 0][rr] = v.x * 0.125f;
    Qt[d4 + 1][rr] = v.y * 0.125f;
    Qt[d4 + 2][rr] = v.z * 0.125f;
    Qt[d4 + 3][rr] = v.w * 0.125f;
  }

  float o[4][4];
#pragma unroll
  for (int i = 0; i < 4; i++)
#pragma unroll
    for (int j = 0; j < 4; j++) o[i][j] = 0.0f;
  float mrow[4] = {-CUDART_INF_F, -CUDART_INF_F, -CUDART_INF_F, -CUDART_INF_F};
  float lrow[4] = {0.0f, 0.0f, 0.0f, 0.0f};

  for (int jt = 0; jt <= qx; jt++) {
    const float* kp = kc + base + (size_t)jt * 64 * DH;
    __syncthreads();
#pragma unroll
    for (int it = 0; it < 4; it++) {
      const int idx = tid + it * 256;
      const int cc = idx >> 4;
      const int d4 = (idx & 15) << 2;
      const float4 v = *reinterpret_cast<const float4*>(kp + cc * DH + d4);
      KV[d4 + 0][cc] = v.x; KV[d4 + 1][cc] = v.y; KV[d4 + 2][cc] = v.z; KV[d4 + 3][cc] = v.w;
    }
    __syncthreads();

    float s[4][4];
#pragma unroll
    for (int i = 0; i < 4; i++)
#pragma unroll
      for (int j = 0; j < 4; j++) s[i][j] = 0.0f;
#pragma unroll
    for (int d = 0; d < 64; d++) {
      const float4 qv = *reinterpret_cast<const float4*>(&Qt[d][r0]);
      const float4 kv = *reinterpret_cast<const float4*>(&KV[d][c0]);
      const float qa[4] = {qv.x, qv.y, qv.z, qv.w};
      const float ka[4] = {kv.x, kv.y, kv.z, kv.w};
#pragma unroll
      for (int i = 0; i < 4; i++)
#pragma unroll
        for (int j = 0; j < 4; j++) s[i][j] += qa[i] * ka[j];
    }
    if (jt == qx) {
#pragma unroll
      for (int i = 0; i < 4; i++)
#pragma unroll
        for (int j = 0; j < 4; j++)
          if (c0 + j > r0 + i) s[i][j] = -CUDART_INF_F;
    }

    float rm[4], rs[4], mnew[4], alpha[4];
#pragma unroll
    for (int i = 0; i < 4; i++)
      rm[i] = fmaxf(fmaxf(s[i][0], s[i][1]), fmaxf(s[i][2], s[i][3]));
#pragma unroll
    for (int off = 8; off > 0; off >>= 1)
#pragma unroll
      for (int i = 0; i < 4; i++)
        rm[i] = fmaxf(rm[i], __shfl_xor_sync(0xffffffffu, rm[i], off));
#pragma unroll
    for (int i = 0; i < 4; i++) {
      mnew[i]  = fmaxf(mrow[i], rm[i]);
      alpha[i] = __expf(mrow[i] - mnew[i]);
      mrow[i]  = mnew[i];
      rs[i]    = 0.0f;
    }
#pragma unroll
    for (int i = 0; i < 4; i++)
#pragma unroll
      for (int j = 0; j < 4; j++) {
        const float p = __expf(s[i][j] - mnew[i]);
        Pt[c0 + j][r0 + i] = p;
        rs[i] += p;
      }
#pragma unroll
    for (int off = 8; off > 0; off >>= 1)
#pragma unroll
      for (int i = 0; i < 4; i++)
        rs[i] += __shfl_xor_sync(0xffffffffu, rs[i], off);
#pragma unroll
    for (int i = 0; i < 4; i++) {
      lrow[i] = lrow[i] * alpha[i] + rs[i];
#pragma unroll
      for (int j = 0; j < 4; j++) o[i][j] *= alpha[i];
    }
    __syncthreads();

    const float* vp = vc + base + (size_t)jt * 64 * DH;
#pragma unroll
    for (int it = 0; it < 4; it++) {
      const int idx = tid + it * 256;
      const int kk = idx >> 4;
      const int d4 = (idx & 15) << 2;
      *reinterpret_cast<float4*>(&KV[kk][d4]) =
          *reinterpret_cast<const float4*>(vp + kk * DH + d4);
    }
    __syncthreads();
#pragma unroll
    for (int k = 0; k < 64; k++) {
      const float4 pv = *reinterpret_cast<const float4*>(&Pt[k][r0]);
      const float4 vv = *reinterpret_cast<const float4*>(&KV[k][c0]);
      const float pa[4] = {pv.x, pv.y, pv.z, pv.w};
      const float va[4] = {vv.x, vv.y, vv.z, vv.w};
#pragma unroll
      for (int i = 0; i < 4; i++)
#pragma unroll
        for (int j = 0; j < 4; j++) o[i][j] += pa[i] * va[j];
    }
  }

  const int b = bh >> 4, h = bh & 15;
#pragma unroll
  for (int i = 0; i < 4; i++) {
    const float inv = 1.0f / lrow[i];
    const int t = qx * 64 + r0 + i;
    const size_t off = ((size_t)(b * TSEQ + t)) * DMODEL + h * DH + c0;
    float4 ov = make_float4(o[i][0] * inv, o[i][1] * inv, o[i][2] * inv, o[i][3] * inv);
    *reinterpret_cast<float4*>(g_attn + off) = ov;
  }
}

// ---------------- silu(gate) * up ----------------
__global__ __launch_bounds__(256) void silu_mul_kernel() {
  const int idx = blockIdx.x * 256 + threadIdx.x;
  float4 g = reinterpret_cast<const float4*>(g_gate)[idx];
  const float4 u = reinterpret_cast<const float4*>(g_up)[idx];
  g.x = (g.x / (1.0f + __expf(-g.x))) * u.x;
  g.y = (g.y / (1.0f + __expf(-g.y))) * u.y;
  g.z = (g.z / (1.0f + __expf(-g.z))) * u.z;
  g.w = (g.w / (1.0f + __expf(-g.w))) * u.w;
  reinterpret_cast<float4*>(g_gate)[idx] = g;
}

// ---------------- launch ----------------
extern "C" void kernel_launch(void* const* d_in, const int* in_sizes, int n_in,
                              void* d_out, int out_size) {
  const float* x       = (const float*)d_in[0];
  const float* w_norm1 = (const float*)d_in[1];
  const float* w_qkv   = (const float*)d_in[2];
  const float* w_proj  = (const float*)d_in[3];
  const float* w_norm2 = (const float*)d_in[4];
  const float* w_gate  = (const float*)d_in[5];
  const float* w_up    = (const float*)d_in[6];
  const float* w_down  = (const float*)d_in[7];

  float* out_x = (float*)d_out;
  float* kc    = out_x + (size_t)MTOK * DMODEL;
  float* vc    = kc    + (size_t)MTOK * DMODEL;

  // opt in to >48KB dynamic smem (host-side attribute set; not a stream op)
  cudaFuncSetAttribute(gemm_bf3<DMODEL, 0, 0, 0>, cudaFuncAttributeMaxDynamicSharedMemorySize, GB_SMEM);
  cudaFuncSetAttribute(gemm_bf3<DMODEL, 1, 1, 1>, cudaFuncAttributeMaxDynamicSharedMemorySize, GB_SMEM);
  cudaFuncSetAttribute(gemm_bf3<DMODEL, 0, 2, 0>, cudaFuncAttributeMaxDynamicSharedMemorySize, GB_SMEM);
  cudaFuncSetAttribute(gemm_bf3<DMODEL, 0, 3, 0>, cudaFuncAttributeMaxDynamicSharedMemorySize, GB_SMEM);
  cudaFuncSetAttribute(gemm_bf3<DFF,    2, 4, 2>, cudaFuncAttributeMaxDynamicSharedMemorySize, GB_SMEM);

  // 1) h = rmsnorm(x) * w_norm1
  rmsnorm_kernel<0><<<MTOK, 256>>>(x, w_norm1);
  // 2) qkv = h @ w_qkv^T
  gemm_bf3<DMODEL, 0, 0, 0><<<dim3(3 * DMODEL / 128, MTOK / 128), 256, GB_SMEM>>>(
      w_qkv, nullptr, nullptr, 3 * DMODEL);
  // 3) scatter q / k_cache / v_cache
  scatter_qkv_kernel<<<MTOK * 768 / 256, 256>>>(kc, vc);
  // 4) causal flash attention
  attention_kernel<<<dim3(TSEQ / 64, NBATCH * NH), 256>>>(kc, vc);
  // 5) x1 = attn @ w_proj^T + x
  gemm_bf3<DMODEL, 1, 1, 1><<<dim3(DMODEL / 128, MTOK / 128), 256, GB_SMEM>>>(
      w_proj, nullptr, x, DMODEL);
  // 6) h2 = rmsnorm(x1) * w_norm2
  rmsnorm_kernel<1><<<MTOK, 256>>>(nullptr, w_norm2);
  // 7) gate / up
  gemm_bf3<DMODEL, 0, 2, 0><<<dim3(DFF / 128, MTOK / 128), 256, GB_SMEM>>>(
      w_gate, nullptr, nullptr, DFF);
  gemm_bf3<DMODEL, 0, 3, 0><<<dim3(DFF / 128, MTOK / 128), 256, GB_SMEM>>>(
      w_up, nullptr, nullptr, DFF);
  // 8) act = silu(gate) * up
  silu_mul_kernel<<<MTOK * DFF / 4 / 256, 256>>>();
  // 9) out_x = act @ w_down^T + x1
  gemm_bf3<DFF, 2, 4, 2><<<dim3(DMODEL / 128, MTOK / 128), 256, GB_SMEM>>>(
      w_down, out_x, nullptr, DMODEL);
}

// round 7
// speedup vs baseline: 1.7095x; 1.2688x over previous
#include <cuda_runtime.h>
#include <cuda_bf16.h>
#include <math_constants.h>
#include <cstdint>

// Problem constants
#define NBATCH 2
#define TSEQ   2048
#define DMODEL 1024
#define NH     16
#define DH     64
#define DFF    4096
#define MTOK   (NBATCH * TSEQ)   // 4096 rows

// ---------------- scratch (static device arrays; no allocation) ----------------
__device__ float g_h   [MTOK * DMODEL];
__device__ float g_qkv [MTOK * 3 * DMODEL];
__device__ float g_q   [MTOK * DMODEL];
__device__ float g_attn[MTOK * DMODEL];
__device__ float g_x1  [MTOK * DMODEL];
__device__ float g_gate[MTOK * DFF];
__device__ float g_up  [MTOK * DFF];
// bf16 hi/lo pre-split K and V caches ([B,H,T,DH] like kc/vc)
__device__ __align__(16) __nv_bfloat16 g_kh[MTOK * DMODEL];
__device__ __align__(16) __nv_bfloat16 g_kl[MTOK * DMODEL];
__device__ __align__(16) __nv_bfloat16 g_vh[MTOK * DMODEL];
__device__ __align__(16) __nv_bfloat16 g_vl[MTOK * DMODEL];

// ==================== bf16 helpers ====================
__device__ __forceinline__ uint32_t pack_bf2(__nv_bfloat16 lo, __nv_bfloat16 hi) {
  __nv_bfloat162 t;
  t.x = lo;  // low 16 bits = first (smaller k) element
  t.y = hi;
  return *reinterpret_cast<uint32_t*>(&t);
}
__device__ __forceinline__ void split_bf(float x, __nv_bfloat16& h, __nv_bfloat16& l) {
  h = __float2bfloat16_rn(x);
  l = __float2bfloat16_rn(x - __bfloat162float(h));
}
// pack pair (x,y) to bf16x2 hi; residual pair to lo
__device__ __forceinline__ uint32_t pk2(float x, float y, uint32_t& lo) {
  __nv_bfloat16 hx = __float2bfloat16_rn(x), hy = __float2bfloat16_rn(y);
  lo = pack_bf2(__float2bfloat16_rn(x - __bfloat162float(hx)),
                __float2bfloat16_rn(y - __bfloat162float(hy)));
  return pack_bf2(hx, hy);
}
// mma.sync m16n8k16 row.col f32.bf16.bf16.f32
__device__ __forceinline__ void mma16816(float* c, const uint32_t* a, uint32_t b0, uint32_t b1) {
  asm("mma.sync.aligned.m16n8k16.row.col.f32.bf16.bf16.f32 "
      "{%0,%1,%2,%3}, {%4,%5,%6,%7}, {%8,%9}, {%0,%1,%2,%3};"
      : "+f"(c[0]), "+f"(c[1]), "+f"(c[2]), "+f"(c[3])
      : "r"(a[0]), "r"(a[1]), "r"(a[2]), "r"(a[3]), "r"(b0), "r"(b1));
}
__device__ __forceinline__ void ldsm4t(uint32_t& r0, uint32_t& r1, uint32_t& r2, uint32_t& r3,
                                       uint32_t addr) {
  asm volatile("ldmatrix.sync.aligned.m8n8.x4.trans.shared.b16 {%0,%1,%2,%3}, [%4];"
               : "=r"(r0), "=r"(r1), "=r"(r2), "=r"(r3) : "r"(addr));
}
__device__ __forceinline__ uint32_t smem_u32(const void* p) {
  uint32_t a;
  asm("{ .reg .u64 t; cvta.to.shared.u64 t, %1; cvt.u32.u64 %0, t; }" : "=r"(a) : "l"(p));
  return a;
}
__device__ __forceinline__ void cp16(uint32_t d, const void* s) {
  asm volatile("cp.async.cg.shared.global [%0], [%1], 16;" :: "r"(d), "l"(s));
}
#define CP_COMMIT() asm volatile("cp.async.commit_group;" ::: "memory")
#define CP_WAIT0()  asm volatile("cp.async.wait_group 0;" ::: "memory")
#define CP_WAIT1()  asm volatile("cp.async.wait_group 1;" ::: "memory")

// ==================== bf16 3-split tensor-core GEMM (unchanged, validated) =====
#define GB_ROWPAD   36
#define GB_MAT      (128 * GB_ROWPAD * 2)
#define GB_STAGE    (4 * GB_MAT)
#define GB_SMEM     (2 * GB_STAGE)

template <int KDIM, int ASEL, int CSEL, int RSEL>
__global__ __launch_bounds__(256, 1) void gemm_bf3(
    const float* __restrict__ Bw, float* __restrict__ Cext,
    const float* __restrict__ Rext, int N) {
  constexpr int NCH = KDIM / 32;
  const float* __restrict__ A = (ASEL == 0) ? g_h : (ASEL == 1) ? g_attn : g_gate;
  float* __restrict__ C = (CSEL == 0) ? g_qkv : (CSEL == 1) ? g_x1
                        : (CSEL == 2) ? g_gate : (CSEL == 3) ? g_up : Cext;
  const float* __restrict__ R = (RSEL == 2) ? g_x1 : Rext;

  extern __shared__ __align__(16) char smem[];
  const int tid = threadIdx.x;
  const int wid = tid >> 5, lane = tid & 31;
  const int wm = wid >> 2, wn = wid & 3;
  const int r = lane >> 2, cq = lane & 3;
  const int bm = blockIdx.y * 128, bn = blockIdx.x * 128;

  const int lrow = tid >> 1;
  const int lq   = (tid & 1) * 16;
  const float* Ap = A  + (size_t)(bm + lrow) * KDIM + lq;
  const float* Bp = Bw + (size_t)(bn + lrow) * KDIM + lq;

  float acc[4][4][4];
#pragma unroll
  for (int f = 0; f < 4; f++)
#pragma unroll
    for (int n = 0; n < 4; n++)
#pragma unroll
      for (int i = 0; i < 4; i++) acc[f][n][i] = 0.0f;

  float4 av[4], bv[4];
#pragma unroll
  for (int i = 0; i < 4; i++) {
    av[i] = *reinterpret_cast<const float4*>(Ap + 4 * i);
    bv[i] = *reinterpret_cast<const float4*>(Bp + 4 * i);
  }

  for (int ch = 0; ch < NCH; ++ch) {
    char* stage = smem + (ch & 1) * GB_STAGE;
#pragma unroll
    for (int i = 0; i < 4; i++) {
      const int k0 = lq + 4 * i;
      const uint32_t boff = (uint32_t)(lrow * GB_ROWPAD + k0) * 2u;
      __nv_bfloat16 hx, lx, hy, ly, hz, lz, hw, lw;
      split_bf(av[i].x, hx, lx); split_bf(av[i].y, hy, ly);
      split_bf(av[i].z, hz, lz); split_bf(av[i].w, hw, lw);
      *reinterpret_cast<uint2*>(stage + 0 * GB_MAT + boff) =
          make_uint2(pack_bf2(hx, hy), pack_bf2(hz, hw));
      *reinterpret_cast<uint2*>(stage + 1 * GB_MAT + boff) =
          make_uint2(pack_bf2(lx, ly), pack_bf2(lz, lw));
      split_bf(bv[i].x, hx, lx); split_bf(bv[i].y, hy, ly);
      split_bf(bv[i].z, hz, lz); split_bf(bv[i].w, hw, lw);
      *reinterpret_cast<uint2*>(stage + 2 * GB_MAT + boff) =
          make_uint2(pack_bf2(hx, hy), pack_bf2(hz, hw));
      *reinterpret_cast<uint2*>(stage + 3 * GB_MAT + boff) =
          make_uint2(pack_bf2(lx, ly), pack_bf2(lz, lw));
    }
    __syncthreads();

    if (ch + 1 < NCH) {
      const float* Ap2 = Ap + (ch + 1) * 32;
      const float* Bp2 = Bp + (ch + 1) * 32;
#pragma unroll
      for (int i = 0; i < 4; i++) {
        av[i] = *reinterpret_cast<const float4*>(Ap2 + 4 * i);
        bv[i] = *reinterpret_cast<const float4*>(Bp2 + 4 * i);
      }
    }

    const uint32_t* pAH = reinterpret_cast<const uint32_t*>(stage + 0 * GB_MAT);
    const uint32_t* pAL = reinterpret_cast<const uint32_t*>(stage + 1 * GB_MAT);
    const uint32_t* pBH = reinterpret_cast<const uint32_t*>(stage + 2 * GB_MAT);
    const uint32_t* pBL = reinterpret_cast<const uint32_t*>(stage + 3 * GB_MAT);
#pragma unroll
    for (int ks = 0; ks < 2; ks++) {
      const int kc = ks * 8 + cq;
      uint32_t ah[4][4], al[4][4];
#pragma unroll
      for (int f = 0; f < 4; f++) {
        const int base = (wm * 64 + f * 16 + r) * (GB_ROWPAD / 2) + kc;
        ah[f][0] = pAH[base];       ah[f][1] = pAH[base + 8 * (GB_ROWPAD / 2)];
        ah[f][2] = pAH[base + 4];   ah[f][3] = pAH[base + 8 * (GB_ROWPAD / 2) + 4];
        al[f][0] = pAL[base];       al[f][1] = pAL[base + 8 * (GB_ROWPAD / 2)];
        al[f][2] = pAL[base + 4];   al[f][3] = pAL[base + 8 * (GB_ROWPAD / 2) + 4];
      }
#pragma unroll
      for (int nf = 0; nf < 4; nf++) {
        const int bb = (wn * 32 + nf * 8 + r) * (GB_ROWPAD / 2) + kc;
        const uint32_t bh0 = pBH[bb], bh1 = pBH[bb + 4];
        const uint32_t bl0 = pBL[bb], bl1 = pBL[bb + 4];
#pragma unroll
        for (int f = 0; f < 4; f++) {
          mma16816(acc[f][nf], ah[f], bh0, bh1);
          mma16816(acc[f][nf], ah[f], bl0, bl1);
          mma16816(acc[f][nf], al[f], bh0, bh1);
        }
      }
    }
    __syncthreads();
  }

#pragma unroll
  for (int f = 0; f < 4; f++) {
    const int row0 = bm + wm * 64 + f * 16 + r;
#pragma unroll
    for (int nf = 0; nf < 4; nf++) {
      const int col = bn + wn * 32 + nf * 8 + cq * 2;
      const size_t o0 = (size_t)row0 * N + col;
      const size_t o1 = o0 + (size_t)8 * N;
      float2 v0 = make_float2(acc[f][nf][0], acc[f][nf][1]);
      float2 v1 = make_float2(acc[f][nf][2], acc[f][nf][3]);
      if (RSEL != 0) {
        const float2 r0 = *reinterpret_cast<const float2*>(R + o0);
        const float2 r1 = *reinterpret_cast<const float2*>(R + o1);
        v0.x += r0.x; v0.y += r0.y; v1.x += r1.x; v1.y += r1.y;
      }
      *reinterpret_cast<float2*>(C + o0) = v0;
      *reinterpret_cast<float2*>(C + o1) = v1;
    }
  }
}

// ---------------- RMSNorm ----------------
template <int SRC>
__global__ __launch_bounds__(256) void rmsnorm_kernel(
    const float* __restrict__ xin, const float* __restrict__ w) {
  const float* __restrict__ x = (SRC == 0) ? xin : g_x1;
  const int row = blockIdx.x;
  const int t = threadIdx.x;
  const float4 v = reinterpret_cast<const float4*>(x)[row * 256 + t];
  float ss = v.x * v.x + v.y * v.y + v.z * v.z + v.w * v.w;
#pragma unroll
  for (int o = 16; o > 0; o >>= 1) ss += __shfl_xor_sync(0xffffffffu, ss, o);
  __shared__ float sbuf[8];
  if ((t & 31) == 0) sbuf[t >> 5] = ss;
  __syncthreads();
  float tot = sbuf[0] + sbuf[1] + sbuf[2] + sbuf[3] + sbuf[4] + sbuf[5] + sbuf[6] + sbuf[7];
  const float r = rsqrtf(tot * (1.0f / DMODEL) + 1e-6f);
  const float4 wv = reinterpret_cast<const float4*>(w)[t];
  float4 o4 = make_float4(v.x * r * wv.x, v.y * r * wv.y, v.z * r * wv.z, v.w * r * wv.w);
  reinterpret_cast<float4*>(g_h)[row * 256 + t] = o4;
}

// ---------------- scatter qkv (+ bf16 hi/lo split of K and V) ----------------
__global__ __launch_bounds__(256) void scatter_qkv_kernel(float* __restrict__ kc,
                                                          float* __restrict__ vc) {
  const int idx = blockIdx.x * 256 + threadIdx.x;
  const float4 v = reinterpret_cast<const float4*>(g_qkv)[idx];
  const int row = idx / 768;
  const int col = (idx - row * 768) << 2;
  const int s  = col >> 10;
  const int hd = col & 1023;
  const int b  = row >> 11;
  const int t  = row & 2047;
  const size_t dst = ((size_t)(b * NH + (hd >> 6)) * TSEQ + t) * DH + (hd & 63);
  if (s == 0) {
    *reinterpret_cast<float4*>(g_q + dst) = v;
  } else {
    __nv_bfloat16 hx, lx, hy, ly, hz, lz, hw, lw;
    split_bf(v.x, hx, lx); split_bf(v.y, hy, ly);
    split_bf(v.z, hz, lz); split_bf(v.w, hw, lw);
    const uint2 hi = make_uint2(pack_bf2(hx, hy), pack_bf2(hz, hw));
    const uint2 lo = make_uint2(pack_bf2(lx, ly), pack_bf2(lz, lw));
    if (s == 1) {
      *reinterpret_cast<float4*>(kc + dst) = v;
      *reinterpret_cast<uint2*>(g_kh + dst) = hi;
      *reinterpret_cast<uint2*>(g_kl + dst) = lo;
    } else {
      *reinterpret_cast<float4*>(vc + dst) = v;
      *reinterpret_cast<uint2*>(g_vh + dst) = hi;
      *reinterpret_cast<uint2*>(g_vl + dst) = lo;
    }
  }
}

// ==================== tensor-core flash attention ====================
// CTA: 128 q-rows x one (b,h). 8 warps, each owns 16 q-rows. k-tiles of 64.
// K/V pre-split bf16 hi/lo in gmem; cp.async double-buffered into smem.
// S = Q K^T and O += P V both via 3-split mma.sync (hi*hi + hi*lo + lo*hi).
#define ATT_PADB  144                 // bytes per 64-elem bf16 row (72 elems)
#define ATT_MAT   (64 * ATT_PADB)     // 9216 bytes
#define ATT_STAGE (4 * ATT_MAT)       // Kh,Kl,Vh,Vl
#define ATT_SMEM  (2 * ATT_STAGE)     // 73728

__global__ __launch_bounds__(256, 1) void attention_tc() {
  extern __shared__ __align__(128) char asmem[];
  const uint32_t smemB = smem_u32(asmem);
  const int tid = threadIdx.x, wid = tid >> 5, lane = tid & 31;
  const int g = lane >> 2, cq = lane & 3;
  const int qx = blockIdx.x, bh = blockIdx.y;
  const int njt = 2 * (qx + 1);
  const size_t cbase = (size_t)bh * TSEQ * DH;

  // ---- Q fragments (hi/lo), pre-scaled by 1/sqrt(DH) ----
  uint32_t qh[4][4], ql[4][4];
  {
    const int qr0 = qx * 128 + wid * 16 + g;
    const float* qp = g_q + cbase;
#pragma unroll
    for (int ki = 0; ki < 4; ki++)
#pragma unroll
      for (int j = 0; j < 4; j++) {
        const int rr = qr0 + (j & 1) * 8;
        const int kk = ki * 16 + cq * 2 + (j >> 1) * 8;
        float2 v = *reinterpret_cast<const float2*>(qp + (size_t)rr * DH + kk);
        v.x *= 0.125f; v.y *= 0.125f;
        qh[ki][j] = pk2(v.x, v.y, ql[ki][j]);
      }
  }

  float o[8][4];
#pragma unroll
  for (int n = 0; n < 8; n++)
#pragma unroll
    for (int i = 0; i < 4; i++) o[n][i] = 0.0f;
  float m0 = -CUDART_INF_F, m1 = -CUDART_INF_F, l0 = 0.0f, l1 = 0.0f;

  // loader mapping: 256 threads, each 32B (2x cp16) per matrix row-chunk
  const int lrow = tid >> 2;           // 0..63 (k row)
  const int lc   = (tid & 3) * 32;     // byte offset in 128B gmem row
  const uint32_t sdst0 = (uint32_t)(lrow * ATT_PADB + lc);

  // ldmatrix lane address components
  const int vt = lane >> 3, vlr = lane & 7;
  const uint32_t vrow = (uint32_t)(((vt & 1) * 8 + vlr) * ATT_PADB);
  const uint32_t vcol = (uint32_t)((vt >> 1) * 16);

  // prologue: issue tile 0
  {
    const size_t gb = cbase;  // jt = 0
    const char* k0 = reinterpret_cast<const char*>(g_kh + gb) + lrow * 128 + lc;
    const char* k1 = reinterpret_cast<const char*>(g_kl + gb) + lrow * 128 + lc;
    const char* v0 = reinterpret_cast<const char*>(g_vh + gb) + lrow * 128 + lc;
    const char* v1 = reinterpret_cast<const char*>(g_vl + gb) + lrow * 128 + lc;
    const uint32_t d = smemB + sdst0;
    cp16(d + 0 * ATT_MAT, k0); cp16(d + 0 * ATT_MAT + 16, k0 + 16);
    cp16(d + 1 * ATT_MAT, k1); cp16(d + 1 * ATT_MAT + 16, k1 + 16);
    cp16(d + 2 * ATT_MAT, v0); cp16(d + 2 * ATT_MAT + 16, v0 + 16);
    cp16(d + 3 * ATT_MAT, v1); cp16(d + 3 * ATT_MAT + 16, v1 + 16);
    CP_COMMIT();
  }

  for (int jt = 0; jt < njt; jt++) {
    const uint32_t stg = smemB + (uint32_t)(jt & 1) * ATT_STAGE;
    if (jt + 1 < njt) {
      const size_t gb = cbase + (size_t)(jt + 1) * 64 * DH;
      const char* k0 = reinterpret_cast<const char*>(g_kh + gb) + lrow * 128 + lc;
      const char* k1 = reinterpret_cast<const char*>(g_kl + gb) + lrow * 128 + lc;
      const char* v0 = reinterpret_cast<const char*>(g_vh + gb) + lrow * 128 + lc;
      const char* v1 = reinterpret_cast<const char*>(g_vl + gb) + lrow * 128 + lc;
      const uint32_t d = smemB + (uint32_t)((jt + 1) & 1) * ATT_STAGE + sdst0;
      cp16(d + 0 * ATT_MAT, k0); cp16(d + 0 * ATT_MAT + 16, k0 + 16);
      cp16(d + 1 * ATT_MAT, k1); cp16(d + 1 * ATT_MAT + 16, k1 + 16);
      cp16(d + 2 * ATT_MAT, v0); cp16(d + 2 * ATT_MAT + 16, v0 + 16);
      cp16(d + 3 * ATT_MAT, v1); cp16(d + 3 * ATT_MAT + 16, v1 + 16);
      CP_COMMIT();
      CP_WAIT1();
    } else {
      CP_WAIT0();
    }
    __syncthreads();

    const char* khp = asmem + (jt & 1) * ATT_STAGE;
    const char* klp = khp + ATT_MAT;
    const uint32_t vh_b = stg + 2 * ATT_MAT;
    const uint32_t vl_b = stg + 3 * ATT_MAT;

    // ---- S = Q K^T ----
    float s[8][4];
#pragma unroll
    for (int n = 0; n < 8; n++)
#pragma unroll
      for (int i = 0; i < 4; i++) s[n][i] = 0.0f;
#pragma unroll
    for (int nf = 0; nf < 8; nf++) {
      const int rb = (nf * 8 + g) * ATT_PADB;
#pragma unroll
      for (int ki = 0; ki < 4; ki++) {
        const int off = rb + (ki * 8 + cq) * 4;
        const uint32_t kh0 = *reinterpret_cast<const uint32_t*>(khp + off);
        const uint32_t kh1 = *reinterpret_cast<const uint32_t*>(khp + off + 16);
        const uint32_t kl0 = *reinterpret_cast<const uint32_t*>(klp + off);
        const uint32_t kl1 = *reinterpret_cast<const uint32_t*>(klp + off + 16);
        mma16816(s[nf], qh[ki], kh0, kh1);
        mma16816(s[nf], qh[ki], kl0, kl1);
        mma16816(s[nf], ql[ki], kh0, kh1);
      }
    }

    // ---- causal mask (only the last two k-tiles can cross the diagonal) ----
    if (jt >= 2 * qx) {
      const int colb = jt * 64 + cq * 2;
      const int rowb = qx * 128 + wid * 16 + g;
#pragma unroll
      for (int nf = 0; nf < 8; nf++) {
        const int c0 = colb + nf * 8;
        if (c0     > rowb)     s[nf][0] = -CUDART_INF_F;
        if (c0 + 1 > rowb)     s[nf][1] = -CUDART_INF_F;
        if (c0     > rowb + 8) s[nf][2] = -CUDART_INF_F;
        if (c0 + 1 > rowb + 8) s[nf][3] = -CUDART_INF_F;
      }
    }

    // ---- online softmax (rows g and g+8; quad reduction) ----
    float rm0 = -CUDART_INF_F, rm1 = -CUDART_INF_F;
#pragma unroll
    for (int nf = 0; nf < 8; nf++) {
      rm0 = fmaxf(rm0, fmaxf(s[nf][0], s[nf][1]));
      rm1 = fmaxf(rm1, fmaxf(s[nf][2], s[nf][3]));
    }
    rm0 = fmaxf(rm0, __shfl_xor_sync(0xffffffffu, rm0, 1));
    rm0 = fmaxf(rm0, __shfl_xor_sync(0xffffffffu, rm0, 2));
    rm1 = fmaxf(rm1, __shfl_xor_sync(0xffffffffu, rm1, 1));
    rm1 = fmaxf(rm1, __shfl_xor_sync(0xffffffffu, rm1, 2));
    const float mn0 = fmaxf(m0, rm0), mn1 = fmaxf(m1, rm1);
    const float al0 = __expf(m0 - mn0), al1 = __expf(m1 - mn1);
    m0 = mn0; m1 = mn1;
    float sum0 = 0.0f, sum1 = 0.0f;
#pragma unroll
    for (int nf = 0; nf < 8; nf++) {
      s[nf][0] = __expf(s[nf][0] - mn0);
      s[nf][1] = __expf(s[nf][1] - mn0);
      s[nf][2] = __expf(s[nf][2] - mn1);
      s[nf][3] = __expf(s[nf][3] - mn1);
      sum0 += s[nf][0] + s[nf][1];
      sum1 += s[nf][2] + s[nf][3];
    }
    sum0 += __shfl_xor_sync(0xffffffffu, sum0, 1);
    sum0 += __shfl_xor_sync(0xffffffffu, sum0, 2);
    sum1 += __shfl_xor_sync(0xffffffffu, sum1, 1);
    sum1 += __shfl_xor_sync(0xffffffffu, sum1, 2);
    l0 = l0 * al0 + sum0;
    l1 = l1 * al1 + sum1;
#pragma unroll
    for (int n = 0; n < 8; n++) {
      o[n][0] *= al0; o[n][1] *= al0; o[n][2] *= al1; o[n][3] *= al1;
    }

    // ---- pack P fragments (C-layout == A-layout identity) ----
    uint32_t aph[4][4], apl[4][4];
#pragma unroll
    for (int ki = 0; ki < 4; ki++) {
      aph[ki][0] = pk2(s[2 * ki][0],     s[2 * ki][1],     apl[ki][0]);
      aph[ki][1] = pk2(s[2 * ki][2],     s[2 * ki][3],     apl[ki][1]);
      aph[ki][2] = pk2(s[2 * ki + 1][0], s[2 * ki + 1][1], apl[ki][2]);
      aph[ki][3] = pk2(s[2 * ki + 1][2], s[2 * ki + 1][3], apl[ki][3]);
    }

    // ---- O += P V  (V fragments via ldmatrix.trans) ----
#pragma unroll
    for (int nbp = 0; nbp < 4; nbp++) {
#pragma unroll
      for (int ki = 0; ki < 4; ki++) {
        const uint32_t off = (uint32_t)(ki * 16 * ATT_PADB) + vrow +
                             (uint32_t)(nbp * 32) + vcol;
        uint32_t h0, h1, h2, h3, e0, e1, e2, e3;
        ldsm4t(h0, h1, h2, h3, vh_b + off);
        ldsm4t(e0, e1, e2, e3, vl_b + off);
        mma16816(o[2 * nbp],     aph[ki], h0, h1);
        mma16816(o[2 * nbp],     aph[ki], e0, e1);
        mma16816(o[2 * nbp],     apl[ki], h0, h1);
        mma16816(o[2 * nbp + 1], aph[ki], h2, h3);
        mma16816(o[2 * nbp + 1], aph[ki], e2, e3);
        mma16816(o[2 * nbp + 1], apl[ki], h2, h3);
      }
    }
    __syncthreads();
  }

  // ---- epilogue: O/l -> g_attn [B,T,H*DH] ----
  const float inv0 = 1.0f / l0, inv1 = 1.0f / l1;
  const int b = bh >> 4, h = bh & 15;
  const int t0 = qx * 128 + wid * 16 + g;
#pragma unroll
  for (int nf = 0; nf < 8; nf++) {
    const int col = h * DH + nf * 8 + cq * 2;
    *reinterpret_cast<float2*>(g_attn + ((size_t)(b * TSEQ + t0)) * DMODEL + col) =
        make_float2(o[nf][0] * inv0, o[nf][1] * inv0);
    *reinterpret_cast<float2*>(g_attn + ((size_t)(b * TSEQ + t0 + 8)) * DMODEL + col) =
        make_float2(o[nf][2] * inv1, o[nf][3] * inv1);
  }
}

// ---------------- silu(gate) * up ----------------
__global__ __launch_bounds__(256) void silu_mul_kernel() {
  const int idx = blockIdx.x * 256 + threadIdx.x;
  float4 g = reinterpret_cast<const float4*>(g_gate)[idx];
  const float4 u = reinterpret_cast<const float4*>(g_up)[idx];
  g.x = (g.x / (1.0f + __expf(-g.x))) * u.x;
  g.y = (g.y / (1.0f + __expf(-g.y))) * u.y;
  g.z = (g.z / (1.0f + __expf(-g.z))) * u.z;
  g.w = (g.w / (1.0f + __expf(-g.w))) * u.w;
  reinterpret_cast<float4*>(g_gate)[idx] = g;
}

// ---------------- launch ----------------
extern "C" void kernel_launch(void* const* d_in, const int* in_sizes, int n_in,
                              void* d_out, int out_size) {
  const float* x       = (const float*)d_in[0];
  const float* w_norm1 = (const float*)d_in[1];
  const float* w_qkv   = (const float*)d_in[2];
  const float* w_proj  = (const float*)d_in[3];
  const float* w_norm2 = (const float*)d_in[4];
  const float* w_gate  = (const float*)d_in[5];
  const float* w_up    = (const float*)d_in[6];
  const float* w_down  = (const float*)d_in[7];

  float* out_x = (float*)d_out;
  float* kc    = out_x + (size_t)MTOK * DMODEL;
  float* vc    = kc    + (size_t)MTOK * DMODEL;

  cudaFuncSetAttribute(gemm_bf3<DMODEL, 0, 0, 0>, cudaFuncAttributeMaxDynamicSharedMemorySize, GB_SMEM);
  cudaFuncSetAttribute(gemm_bf3<DMODEL, 1, 1, 1>, cudaFuncAttributeMaxDynamicSharedMemorySize, GB_SMEM);
  cudaFuncSetAttribute(gemm_bf3<DMODEL, 0, 2, 0>, cudaFuncAttributeMaxDynamicSharedMemorySize, GB_SMEM);
  cudaFuncSetAttribute(gemm_bf3<DMODEL, 0, 3, 0>, cudaFuncAttributeMaxDynamicSharedMemorySize, GB_SMEM);
  cudaFuncSetAttribute(gemm_bf3<DFF,    2, 4, 2>, cudaFuncAttributeMaxDynamicSharedMemorySize, GB_SMEM);
  cudaFuncSetAttribute(attention_tc, cudaFuncAttributeMaxDynamicSharedMemorySize, ATT_SMEM);

  // 1) h = rmsnorm(x) * w_norm1
  rmsnorm_kernel<0><<<MTOK, 256>>>(x, w_norm1);
  // 2) qkv = h @ w_qkv^T
  gemm_bf3<DMODEL, 0, 0, 0><<<dim3(3 * DMODEL / 128, MTOK / 128), 256, GB_SMEM>>>(
      w_qkv, nullptr, nullptr, 3 * DMODEL);
  // 3) scatter q / k_cache / v_cache (+ bf16 hi/lo K,V)
  scatter_qkv_kernel<<<MTOK * 768 / 256, 256>>>(kc, vc);
  // 4) causal flash attention (tensor cores)
  attention_tc<<<dim3(TSEQ / 128, NBATCH * NH), 256, ATT_SMEM>>>();
  // 5) x1 = attn @ w_proj^T + x
  gemm_bf3<DMODEL, 1, 1, 1><<<dim3(DMODEL / 128, MTOK / 128), 256, GB_SMEM>>>(
      w_proj, nullptr, x, DMODEL);
  // 6) h2 = rmsnorm(x1) * w_norm2
  rmsnorm_kernel<1><<<MTOK, 256>>>(nullptr, w_norm2);
  // 7) gate / up
  gemm_bf3<DMODEL, 0, 2, 0><<<dim3(DFF / 128, MTOK / 128), 256, GB_SMEM>>>(
      w_gate, nullptr, nullptr, DFF);
  gemm_bf3<DMODEL, 0, 3, 0><<<dim3(DFF / 128, MTOK / 128), 256, GB_SMEM>>>(
      w_up, nullptr, nullptr, DFF);
  // 8) act = silu(gate) * up
  silu_mul_kernel<<<MTOK * DFF / 4 / 256, 256>>>();
  // 9) out_x = act @ w_down^T + x1
  gemm_bf3<DFF, 2, 4, 2><<<dim3(DMODEL / 128, MTOK / 128), 256, GB_SMEM>>>(
      w_down, out_x, nullptr, DMODEL);
}